// round 10
// baseline (speedup 1.0000x reference)
#include <cuda_runtime.h>
#include <cuda_bf16.h>
#include <mma.h>

using namespace nvcuda;

// Problem constants (fixed by the dataset instance)
static constexpr int T_TOK = 2048;
static constexpr int HS    = 2048;
static constexpr int IMZ   = 1408;
static constexpr int NE    = 32;

// Tiling
static constexpr int BM = 64;
static constexpr int BN = 128;
static constexpr int BK = 32;
static constexpr int NTHREADS = 256;      // 8 warps: 2 (m) x 4 (n)
static constexpr int LDA = BK + 8;        // 40 bf16 elems
static constexpr int LDB = BN + 8;        // 136 bf16 elems

// Double-buffered stage sizes (bytes)
static constexpr int GU_STAGE = 45056;    // A hi/lo 2*5120 + G,U hi/lo 4*8704
static constexpr int GU_SMEM  = 2 * GU_STAGE;   // 90112
static constexpr int DN_STAGE = 27648;    // A hi/lo 2*5120 + W hi/lo 2*8704
static constexpr int DN_SMEM  = 2 * DN_STAGE;   // 55296
// Epilogue staging tile (aliases stage memory after the final barrier):
// 64 * 136 * 4 = 34816 bytes.

// Scratch (static device allocations are allowed; cudaMalloc is not)
__device__ float g_inter[(size_t)T_TOK * IMZ];

// ---------------------------------------------------------------------------
// fp32 -> bf16 hi/lo split, packed as uint2 (4 bf16 = 8B) for STS.64 stores.
// hi = rn(x), lo = rn(x - hi). bf16x3 product error ~2^-16 rel.
// ---------------------------------------------------------------------------
__device__ __forceinline__ void split4(float4 v, uint2& hi, uint2& lo) {
    __nv_bfloat16 hx = __float2bfloat16_rn(v.x);
    __nv_bfloat16 hy = __float2bfloat16_rn(v.y);
    __nv_bfloat16 hz = __float2bfloat16_rn(v.z);
    __nv_bfloat16 hw = __float2bfloat16_rn(v.w);
    union { __nv_bfloat162 b2[2]; uint2 u; } H, L;
    H.b2[0] = __halves2bfloat162(hx, hy);
    H.b2[1] = __halves2bfloat162(hz, hw);
    L.b2[0] = __floats2bfloat162_rn(v.x - __bfloat162float(hx),
                                    v.y - __bfloat162float(hy));
    L.b2[1] = __floats2bfloat162_rn(v.z - __bfloat162float(hz),
                                    v.w - __bfloat162float(hw));
    hi = H.u;
    lo = L.u;
}

// Per-block expert offsets via warp shfl inclusive scan of group_sizes.
__device__ __forceinline__ void expert_offsets(const int* __restrict__ gs,
                                               int e, int tid,
                                               int* __restrict__ s_off) {
    if (tid < 32) {
        int g = (tid < NE) ? gs[tid] : 0;
        int v = g;
#pragma unroll
        for (int d = 1; d < 32; d <<= 1) {
            int t = __shfl_up_sync(0xffffffffu, v, d);
            if (tid >= d) v += t;
        }
        if (tid == e) { s_off[1] = v; s_off[0] = v - g; }
    }
}

// ---------------------------------------------------------------------------
// Kernel 1: inter = silu(H @ Wg[e]) * (H @ Wu[e])  per expert group
// Grid: (IMZ/BN, NE).  2-stage smem pipeline, one barrier per k-iter.
// ---------------------------------------------------------------------------
__global__ __launch_bounds__(NTHREADS, 2)
void gateup_kernel(const float* __restrict__ H,    // [T, HS]
                   const float* __restrict__ Wg,   // [E, HS, IMZ]
                   const float* __restrict__ Wu,   // [E, HS, IMZ]
                   const int* __restrict__ gs)
{
    extern __shared__ __align__(16) char ds[];
    __shared__ int s_off[2];

#define GA_HI(s) ((__nv_bfloat16*)(ds + (s) * GU_STAGE))
#define GA_LO(s) ((__nv_bfloat16*)(ds + (s) * GU_STAGE + 5120))
#define GG_HI(s) ((__nv_bfloat16*)(ds + (s) * GU_STAGE + 10240))
#define GG_LO(s) ((__nv_bfloat16*)(ds + (s) * GU_STAGE + 18944))
#define GU_HI(s) ((__nv_bfloat16*)(ds + (s) * GU_STAGE + 27648))
#define GU_LO(s) ((__nv_bfloat16*)(ds + (s) * GU_STAGE + 36352))
    float* sStage = (float*)ds;  // epilogue staging, after final bar

    const int e   = blockIdx.y;
    const int n0  = blockIdx.x * BN;
    const int tid = threadIdx.x;
    const int wid = tid >> 5;
    const int warp_m = wid >> 2;   // 0..1 -> 32 rows each
    const int warp_n = wid & 3;    // 0..3 -> 32 cols each

    expert_offsets(gs, e, tid, s_off);
    __syncthreads();
    const int off0 = s_off[0];
    const int off1 = s_off[1];

    const int rA = tid >> 3;            // + 32*i
    const int cA = (tid & 7) * 4;
    const int rB = tid >> 5;            // + 8*i
    const int cB = (tid & 31) * 4;

    const float* wg = Wg + (size_t)e * HS * IMZ + n0;
    const float* wu = Wu + (size_t)e * HS * IMZ + n0;

    constexpr int NS = HS / BK;  // 64

    for (int row_base = off0; row_base < off1; row_base += BM) {
        const int rows = min(BM, off1 - row_base);

        wmma::fragment<wmma::accumulator, 16, 16, 16, float> accg[2][2], accu[2][2];
#pragma unroll
        for (int m = 0; m < 2; ++m)
#pragma unroll
            for (int n = 0; n < 2; ++n) {
                wmma::fill_fragment(accg[m][n], 0.0f);
                wmma::fill_fragment(accu[m][n], 0.0f);
            }

        float4 ra[2], rg[4], ru[4];
        // ---- prologue: tile 0 -> buf0; tile 1 -> registers ----
#pragma unroll
        for (int i = 0; i < 2; ++i)
            ra[i] = (rA + 32 * i < rows)
                  ? *(const float4*)(H + (size_t)(row_base + rA + 32 * i) * HS + cA)
                  : make_float4(0.f, 0.f, 0.f, 0.f);
#pragma unroll
        for (int i = 0; i < 4; ++i) {
            rg[i] = *(const float4*)(wg + (size_t)(rB + 8 * i) * IMZ + cB);
            ru[i] = *(const float4*)(wu + (size_t)(rB + 8 * i) * IMZ + cB);
        }
#pragma unroll
        for (int i = 0; i < 2; ++i) {
            uint2 hi, lo;
            split4(ra[i], hi, lo);
            *(uint2*)(GA_HI(0) + (rA + 32 * i) * LDA + cA) = hi;
            *(uint2*)(GA_LO(0) + (rA + 32 * i) * LDA + cA) = lo;
        }
#pragma unroll
        for (int i = 0; i < 4; ++i) {
            uint2 hi, lo;
            split4(rg[i], hi, lo);
            *(uint2*)(GG_HI(0) + (rB + 8 * i) * LDB + cB) = hi;
            *(uint2*)(GG_LO(0) + (rB + 8 * i) * LDB + cB) = lo;
            split4(ru[i], hi, lo);
            *(uint2*)(GU_HI(0) + (rB + 8 * i) * LDB + cB) = hi;
            *(uint2*)(GU_LO(0) + (rB + 8 * i) * LDB + cB) = lo;
        }
        // tile 1 into registers
#pragma unroll
        for (int i = 0; i < 2; ++i)
            ra[i] = (rA + 32 * i < rows)
                  ? *(const float4*)(H + (size_t)(row_base + rA + 32 * i) * HS + BK + cA)
                  : make_float4(0.f, 0.f, 0.f, 0.f);
#pragma unroll
        for (int i = 0; i < 4; ++i) {
            rg[i] = *(const float4*)(wg + (size_t)(BK + rB + 8 * i) * IMZ + cB);
            ru[i] = *(const float4*)(wu + (size_t)(BK + rB + 8 * i) * IMZ + cB);
        }
        __syncthreads();

        for (int k = 0; k < NS; ++k) {
            const int b  = k & 1;
            const int nb = b ^ 1;

            // ---- MMA on buf b (warps stagger; tensor pipe stays fed) ----
            __nv_bfloat16* sAhi = GA_HI(b); __nv_bfloat16* sAlo = GA_LO(b);
            __nv_bfloat16* sGhi = GG_HI(b); __nv_bfloat16* sGlo = GG_LO(b);
            __nv_bfloat16* sUhi = GU_HI(b); __nv_bfloat16* sUlo = GU_LO(b);
#pragma unroll
            for (int kk = 0; kk < 2; ++kk) {
                wmma::fragment<wmma::matrix_a, 16, 16, 16, __nv_bfloat16, wmma::row_major> ahi[2], alo[2];
#pragma unroll
                for (int m = 0; m < 2; ++m) {
                    const int ro = (warp_m * 32 + m * 16) * LDA + kk * 16;
                    wmma::load_matrix_sync(ahi[m], sAhi + ro, LDA);
                    wmma::load_matrix_sync(alo[m], sAlo + ro, LDA);
                }
#pragma unroll
                for (int n = 0; n < 2; ++n) {
                    const int co = (kk * 16) * LDB + warp_n * 32 + n * 16;
                    wmma::fragment<wmma::matrix_b, 16, 16, 16, __nv_bfloat16, wmma::row_major>
                        bghi, bglo, buhi, bulo;
                    wmma::load_matrix_sync(bghi, sGhi + co, LDB);
                    wmma::load_matrix_sync(bglo, sGlo + co, LDB);
                    wmma::load_matrix_sync(buhi, sUhi + co, LDB);
                    wmma::load_matrix_sync(bulo, sUlo + co, LDB);
#pragma unroll
                    for (int m = 0; m < 2; ++m) {
                        wmma::mma_sync(accg[m][n], ahi[m], bghi, accg[m][n]);
                        wmma::mma_sync(accg[m][n], ahi[m], bglo, accg[m][n]);
                        wmma::mma_sync(accg[m][n], alo[m], bghi, accg[m][n]);
                        wmma::mma_sync(accu[m][n], ahi[m], buhi, accu[m][n]);
                        wmma::mma_sync(accu[m][n], ahi[m], bulo, accu[m][n]);
                        wmma::mma_sync(accu[m][n], alo[m], buhi, accu[m][n]);
                    }
                }
            }

            // ---- split+store tile k+1 (register-resident) into buf nb ----
            if (k + 1 < NS) {
#pragma unroll
                for (int i = 0; i < 2; ++i) {
                    uint2 hi, lo;
                    split4(ra[i], hi, lo);
                    *(uint2*)(GA_HI(nb) + (rA + 32 * i) * LDA + cA) = hi;
                    *(uint2*)(GA_LO(nb) + (rA + 32 * i) * LDA + cA) = lo;
                }
#pragma unroll
                for (int i = 0; i < 4; ++i) {
                    uint2 hi, lo;
                    split4(rg[i], hi, lo);
                    *(uint2*)(GG_HI(nb) + (rB + 8 * i) * LDB + cB) = hi;
                    *(uint2*)(GG_LO(nb) + (rB + 8 * i) * LDB + cB) = lo;
                    split4(ru[i], hi, lo);
                    *(uint2*)(GU_HI(nb) + (rB + 8 * i) * LDB + cB) = hi;
                    *(uint2*)(GU_LO(nb) + (rB + 8 * i) * LDB + cB) = lo;
                }
            }
            // ---- prefetch tile k+2 into registers ----
            if (k + 2 < NS) {
                const int kn = (k + 2) * BK;
#pragma unroll
                for (int i = 0; i < 2; ++i)
                    ra[i] = (rA + 32 * i < rows)
                          ? *(const float4*)(H + (size_t)(row_base + rA + 32 * i) * HS + kn + cA)
                          : make_float4(0.f, 0.f, 0.f, 0.f);
#pragma unroll
                for (int i = 0; i < 4; ++i) {
                    rg[i] = *(const float4*)(wg + (size_t)(kn + rB + 8 * i) * IMZ + cB);
                    ru[i] = *(const float4*)(wu + (size_t)(kn + rB + 8 * i) * IMZ + cB);
                }
            }
            __syncthreads();
        }

        // ---- epilogue: SwiGLU on fragments, stage via smem, predicated store ----
#pragma unroll
        for (int m = 0; m < 2; ++m)
#pragma unroll
            for (int n = 0; n < 2; ++n) {
#pragma unroll
                for (int i = 0; i < accg[m][n].num_elements; ++i) {
                    float g = accg[m][n].x[i];
                    float u = accu[m][n].x[i];
                    accg[m][n].x[i] = u * g / (1.0f + __expf(-g));
                }
                wmma::store_matrix_sync(
                    sStage + (warp_m * 32 + m * 16) * LDB + warp_n * 32 + n * 16,
                    accg[m][n], LDB, wmma::mem_row_major);
            }
        __syncthreads();
#pragma unroll
        for (int i = 0; i < 8; ++i) {
            int id = tid + i * NTHREADS;
            int r  = id >> 5;
            int c  = (id & 31) * 4;
            if (r < rows) {
                float4 v = *(const float4*)(sStage + r * LDB + c);
                *(float4*)(g_inter + (size_t)(row_base + r) * IMZ + n0 + c) = v;
            }
        }
        __syncthreads();
    }
#undef GA_HI
#undef GA_LO
#undef GG_HI
#undef GG_LO
#undef GU_HI
#undef GU_LO
}

// ---------------------------------------------------------------------------
// Kernel 2: out = inter @ Wd[e]  per expert group
// Grid: (HS/BN, NE).  2-stage smem pipeline, one barrier per k-iter.
// ---------------------------------------------------------------------------
__global__ __launch_bounds__(NTHREADS, 2)
void down_kernel(const float* __restrict__ Wd,   // [E, IMZ, HS]
                 float* __restrict__ Out,        // [T, HS]
                 const int* __restrict__ gs)
{
    extern __shared__ __align__(16) char ds[];
    __shared__ int s_off[2];

#define DA_HI(s) ((__nv_bfloat16*)(ds + (s) * DN_STAGE))
#define DA_LO(s) ((__nv_bfloat16*)(ds + (s) * DN_STAGE + 5120))
#define DW_HI(s) ((__nv_bfloat16*)(ds + (s) * DN_STAGE + 10240))
#define DW_LO(s) ((__nv_bfloat16*)(ds + (s) * DN_STAGE + 18944))
    float* sStage = (float*)ds;

    const int e   = blockIdx.y;
    const int n0  = blockIdx.x * BN;
    const int tid = threadIdx.x;
    const int wid = tid >> 5;
    const int warp_m = wid >> 2;
    const int warp_n = wid & 3;

    expert_offsets(gs, e, tid, s_off);
    __syncthreads();
    const int off0 = s_off[0];
    const int off1 = s_off[1];

    const int rA = tid >> 3;
    const int cA = (tid & 7) * 4;
    const int rB = tid >> 5;
    const int cB = (tid & 31) * 4;

    const float* wd = Wd + (size_t)e * IMZ * HS + n0;

    constexpr int NS = IMZ / BK;  // 44

    for (int row_base = off0; row_base < off1; row_base += BM) {
        const int rows = min(BM, off1 - row_base);

        wmma::fragment<wmma::accumulator, 16, 16, 16, float> acc[2][2];
#pragma unroll
        for (int m = 0; m < 2; ++m)
#pragma unroll
            for (int n = 0; n < 2; ++n) wmma::fill_fragment(acc[m][n], 0.0f);

        float4 ra[2], rw[4];
        // ---- prologue: tile 0 -> buf0; tile 1 -> registers ----
#pragma unroll
        for (int i = 0; i < 2; ++i)
            ra[i] = (rA + 32 * i < rows)
                  ? *(const float4*)(g_inter + (size_t)(row_base + rA + 32 * i) * IMZ + cA)
                  : make_float4(0.f, 0.f, 0.f, 0.f);
#pragma unroll
        for (int i = 0; i < 4; ++i)
            rw[i] = *(const float4*)(wd + (size_t)(rB + 8 * i) * HS + cB);
#pragma unroll
        for (int i = 0; i < 2; ++i) {
            uint2 hi, lo;
            split4(ra[i], hi, lo);
            *(uint2*)(DA_HI(0) + (rA + 32 * i) * LDA + cA) = hi;
            *(uint2*)(DA_LO(0) + (rA + 32 * i) * LDA + cA) = lo;
        }
#pragma unroll
        for (int i = 0; i < 4; ++i) {
            uint2 hi, lo;
            split4(rw[i], hi, lo);
            *(uint2*)(DW_HI(0) + (rB + 8 * i) * LDB + cB) = hi;
            *(uint2*)(DW_LO(0) + (rB + 8 * i) * LDB + cB) = lo;
        }
#pragma unroll
        for (int i = 0; i < 2; ++i)
            ra[i] = (rA + 32 * i < rows)
                  ? *(const float4*)(g_inter + (size_t)(row_base + rA + 32 * i) * IMZ + BK + cA)
                  : make_float4(0.f, 0.f, 0.f, 0.f);
#pragma unroll
        for (int i = 0; i < 4; ++i)
            rw[i] = *(const float4*)(wd + (size_t)(BK + rB + 8 * i) * HS + cB);
        __syncthreads();

        for (int k = 0; k < NS; ++k) {
            const int b  = k & 1;
            const int nb = b ^ 1;

            __nv_bfloat16* sAhi = DA_HI(b); __nv_bfloat16* sAlo = DA_LO(b);
            __nv_bfloat16* sWhi = DW_HI(b); __nv_bfloat16* sWlo = DW_LO(b);
#pragma unroll
            for (int kk = 0; kk < 2; ++kk) {
                wmma::fragment<wmma::matrix_a, 16, 16, 16, __nv_bfloat16, wmma::row_major> ahi[2], alo[2];
#pragma unroll
                for (int m = 0; m < 2; ++m) {
                    const int ro = (warp_m * 32 + m * 16) * LDA + kk * 16;
                    wmma::load_matrix_sync(ahi[m], sAhi + ro, LDA);
                    wmma::load_matrix_sync(alo[m], sAlo + ro, LDA);
                }
#pragma unroll
                for (int n = 0; n < 2; ++n) {
                    const int co = (kk * 16) * LDB + warp_n * 32 + n * 16;
                    wmma::fragment<wmma::matrix_b, 16, 16, 16, __nv_bfloat16, wmma::row_major> bhi, blo;
                    wmma::load_matrix_sync(bhi, sWhi + co, LDB);
                    wmma::load_matrix_sync(blo, sWlo + co, LDB);
#pragma unroll
                    for (int m = 0; m < 2; ++m) {
                        wmma::mma_sync(acc[m][n], ahi[m], bhi, acc[m][n]);
                        wmma::mma_sync(acc[m][n], ahi[m], blo, acc[m][n]);
                        wmma::mma_sync(acc[m][n], alo[m], bhi, acc[m][n]);
                    }
                }
            }

            if (k + 1 < NS) {
#pragma unroll
                for (int i = 0; i < 2; ++i) {
                    uint2 hi, lo;
                    split4(ra[i], hi, lo);
                    *(uint2*)(DA_HI(nb) + (rA + 32 * i) * LDA + cA) = hi;
                    *(uint2*)(DA_LO(nb) + (rA + 32 * i) * LDA + cA) = lo;
                }
#pragma unroll
                for (int i = 0; i < 4; ++i) {
                    uint2 hi, lo;
                    split4(rw[i], hi, lo);
                    *(uint2*)(DW_HI(nb) + (rB + 8 * i) * LDB + cB) = hi;
                    *(uint2*)(DW_LO(nb) + (rB + 8 * i) * LDB + cB) = lo;
                }
            }
            if (k + 2 < NS) {
                const int kn = (k + 2) * BK;
#pragma unroll
                for (int i = 0; i < 2; ++i)
                    ra[i] = (rA + 32 * i < rows)
                          ? *(const float4*)(g_inter + (size_t)(row_base + rA + 32 * i) * IMZ + kn + cA)
                          : make_float4(0.f, 0.f, 0.f, 0.f);
#pragma unroll
                for (int i = 0; i < 4; ++i)
                    rw[i] = *(const float4*)(wd + (size_t)(kn + rB + 8 * i) * HS + cB);
            }
            __syncthreads();
        }

#pragma unroll
        for (int m = 0; m < 2; ++m)
#pragma unroll
            for (int n = 0; n < 2; ++n)
                wmma::store_matrix_sync(
                    sStage + (warp_m * 32 + m * 16) * LDB + warp_n * 32 + n * 16,
                    acc[m][n], LDB, wmma::mem_row_major);
        __syncthreads();
#pragma unroll
        for (int i = 0; i < 8; ++i) {
            int id = tid + i * NTHREADS;
            int r  = id >> 5;
            int c  = (id & 31) * 4;
            if (r < rows) {
                float4 v = *(const float4*)(sStage + r * LDB + c);
                *(float4*)(Out + (size_t)(row_base + r) * HS + n0 + c) = v;
            }
        }
        __syncthreads();
    }
#undef DA_HI
#undef DA_LO
#undef DW_HI
#undef DW_LO
}

// ---------------------------------------------------------------------------
extern "C" void kernel_launch(void* const* d_in, const int* in_sizes, int n_in,
                              void* d_out, int out_size) {
    const float* H  = (const float*)d_in[0];   // hidden_states [T, HS]
    const float* Wg = (const float*)d_in[1];   // gate_kernel   [E, HS, IMZ]
    const float* Wu = (const float*)d_in[2];   // up_kernel     [E, HS, IMZ]
    const float* Wd = (const float*)d_in[3];   // down_kernel   [E, IMZ, HS]
    const int*   gs = (const int*)d_in[4];     // group_sizes   [E]
    float* Out = (float*)d_out;                // [T, HS]

    static bool attr_done = false;
    if (!attr_done) {
        cudaFuncSetAttribute(gateup_kernel,
                             cudaFuncAttributeMaxDynamicSharedMemorySize, GU_SMEM);
        cudaFuncSetAttribute(down_kernel,
                             cudaFuncAttributeMaxDynamicSharedMemorySize, DN_SMEM);
        attr_done = true;
    }

    gateup_kernel<<<dim3(IMZ / BN, NE), NTHREADS, GU_SMEM>>>(H, Wg, Wu, gs);
    down_kernel<<<dim3(HS / BN, NE), NTHREADS, DN_SMEM>>>(Wd, Out, gs);
}

// round 12
// speedup vs baseline: 1.0906x; 1.0906x over previous
#include <cuda_runtime.h>
#include <cuda_bf16.h>
#include <mma.h>
#include <cstdint>

using namespace nvcuda;

// Problem constants (fixed by the dataset instance)
static constexpr int T_TOK = 2048;
static constexpr int HS    = 2048;
static constexpr int IMZ   = 1408;
static constexpr int NE    = 32;

// Tiling
static constexpr int BM = 64;
static constexpr int BN = 128;
static constexpr int BK = 32;
static constexpr int NTHREADS = 256;      // 8 warps: 2 (m) x 4 (n)
static constexpr int LDA = BK + 8;        // 40 bf16 elems (80B rows; 16B-aligned cols)
static constexpr int LDB = BN + 8;        // 136 bf16 elems (272B rows; 16B-aligned cols)

// Stage: A hi/lo 2*5120B + B hi/lo 2*8704B = 27648B; double-buffered.
static constexpr int GEMM_STAGE = 27648;
static constexpr int GEMM_SMEM  = 2 * GEMM_STAGE;   // 55296
// Epilogue staging tile (aliases stage 0/1): 64*136*4 = 34816 <= 55296.

// Scratch (static device allocations are allowed; cudaMalloc is not)
__device__ float g_gate [(size_t)T_TOK * IMZ];
__device__ float g_up   [(size_t)T_TOK * IMZ];
__device__ float g_inter[(size_t)T_TOK * IMZ];

// ---------------------------------------------------------------------------
// fp32 x8 -> bf16 hi/lo split, packed as uint4 (8 bf16 = 16B) for STS.128.
// hi = rn(x), lo = rn(x - hi). bf16x3 product error ~2^-16 rel.
// ---------------------------------------------------------------------------
__device__ __forceinline__ void split8(const float4& a, const float4& b,
                                       uint4& hi, uint4& lo) {
    __nv_bfloat162 h0 = __floats2bfloat162_rn(a.x, a.y);
    __nv_bfloat162 h1 = __floats2bfloat162_rn(a.z, a.w);
    __nv_bfloat162 h2 = __floats2bfloat162_rn(b.x, b.y);
    __nv_bfloat162 h3 = __floats2bfloat162_rn(b.z, b.w);
    float2 f0 = __bfloat1622float2(h0);
    float2 f1 = __bfloat1622float2(h1);
    float2 f2 = __bfloat1622float2(h2);
    float2 f3 = __bfloat1622float2(h3);
    __nv_bfloat162 l0 = __floats2bfloat162_rn(a.x - f0.x, a.y - f0.y);
    __nv_bfloat162 l1 = __floats2bfloat162_rn(a.z - f1.x, a.w - f1.y);
    __nv_bfloat162 l2 = __floats2bfloat162_rn(b.x - f2.x, b.y - f2.y);
    __nv_bfloat162 l3 = __floats2bfloat162_rn(b.z - f3.x, b.w - f3.y);
    hi.x = *(const uint32_t*)&h0; hi.y = *(const uint32_t*)&h1;
    hi.z = *(const uint32_t*)&h2; hi.w = *(const uint32_t*)&h3;
    lo.x = *(const uint32_t*)&l0; lo.y = *(const uint32_t*)&l1;
    lo.z = *(const uint32_t*)&l2; lo.w = *(const uint32_t*)&l3;
}

// ---------------------------------------------------------------------------
// Unified grouped GEMM: Out[t, n] = A[t, :] @ B[e, :, n] for t in expert e's
// row group.  A: [T, K] fp32.  B: [E, K, NTOT] fp32 (n contiguous).
// Persistent blocks loop over (e, n0) tiles.  bf16x3 via HMMA, 2-stage smem
// pipeline with register prefetch, one barrier per k-iter.
// ---------------------------------------------------------------------------
__global__ __launch_bounds__(NTHREADS, 2)
void gemm_tc(const float* __restrict__ A, const float* __restrict__ B,
             float* __restrict__ Out, const int* __restrict__ gs,
             int K, int NTOT, int nx)
{
    extern __shared__ __align__(16) char ds[];
    __shared__ int s_ofs[NE + 1];

#define S_AHI(s) ((__nv_bfloat16*)(ds + (s) * GEMM_STAGE))
#define S_ALO(s) ((__nv_bfloat16*)(ds + (s) * GEMM_STAGE + 5120))
#define S_BHI(s) ((__nv_bfloat16*)(ds + (s) * GEMM_STAGE + 10240))
#define S_BLO(s) ((__nv_bfloat16*)(ds + (s) * GEMM_STAGE + 18944))
    float* sStage = (float*)ds;  // epilogue staging (after final bar)

    const int tid = threadIdx.x;
    const int wid = tid >> 5;
    const int warp_m = wid >> 2;   // 0..1 -> 32 rows
    const int warp_n = wid & 3;    // 0..3 -> 32 cols

    // Full expert-offset prefix once per block.
    if (tid < 32) {
        int g = (tid < NE) ? gs[tid] : 0;
        int v = g;
#pragma unroll
        for (int d = 1; d < 32; d <<= 1) {
            int t = __shfl_up_sync(0xffffffffu, v, d);
            if (tid >= d) v += t;
        }
        if (tid < NE) s_ofs[tid + 1] = v;
        if (tid == 0) s_ofs[0] = 0;
    }
    __syncthreads();

    // Per-thread load coords (8 contiguous fp32 per thread-group)
    const int rA = tid >> 2;            // 0..63
    const int cA = (tid & 3) * 8;       // 0..24
    const int rB = tid >> 4;            // 0..15 (+16 for group 1)
    const int cB = (tid & 15) * 8;      // 0..120

    const int NS = K >> 5;              // K / BK
    const int ntiles = nx * NE;

    for (int t = blockIdx.x; t < ntiles; t += gridDim.x) {
        const int e  = t / nx;
        const int n0 = (t - e * nx) * BN;
        const int off0 = s_ofs[e], off1 = s_ofs[e + 1];
        const float* wb = B + (size_t)e * K * NTOT + n0;

        for (int row_base = off0; row_base < off1; row_base += BM) {
            const int rows = min(BM, off1 - row_base);

            wmma::fragment<wmma::accumulator, 16, 16, 16, float> acc[2][2];
#pragma unroll
            for (int m = 0; m < 2; ++m)
#pragma unroll
                for (int n = 0; n < 2; ++n) wmma::fill_fragment(acc[m][n], 0.0f);

            float4 a0, a1, bb[2][2];
            const float* arow = A + (size_t)(row_base + rA) * K + cA;

            // ---- prologue: tile 0 -> regs -> buf0; tile 1 -> regs ----
            if (rA < rows) { a0 = *(const float4*)arow; a1 = *(const float4*)(arow + 4); }
            else           { a0 = a1 = make_float4(0.f, 0.f, 0.f, 0.f); }
#pragma unroll
            for (int i = 0; i < 2; ++i) {
                const float* brow = wb + (size_t)(rB + 16 * i) * NTOT + cB;
                bb[i][0] = *(const float4*)brow;
                bb[i][1] = *(const float4*)(brow + 4);
            }
            {
                uint4 hi, lo;
                split8(a0, a1, hi, lo);
                *(uint4*)(S_AHI(0) + rA * LDA + cA) = hi;
                *(uint4*)(S_ALO(0) + rA * LDA + cA) = lo;
#pragma unroll
                for (int i = 0; i < 2; ++i) {
                    split8(bb[i][0], bb[i][1], hi, lo);
                    *(uint4*)(S_BHI(0) + (rB + 16 * i) * LDB + cB) = hi;
                    *(uint4*)(S_BLO(0) + (rB + 16 * i) * LDB + cB) = lo;
                }
            }
            if (NS > 1) {
                if (rA < rows) { a0 = *(const float4*)(arow + BK); a1 = *(const float4*)(arow + BK + 4); }
                else           { a0 = a1 = make_float4(0.f, 0.f, 0.f, 0.f); }
#pragma unroll
                for (int i = 0; i < 2; ++i) {
                    const float* brow = wb + (size_t)(BK + rB + 16 * i) * NTOT + cB;
                    bb[i][0] = *(const float4*)brow;
                    bb[i][1] = *(const float4*)(brow + 4);
                }
            }
            __syncthreads();

            for (int k = 0; k < NS; ++k) {
                const int b  = k & 1;
                const int nb = b ^ 1;

                // ---- MMA on buf b ----
                __nv_bfloat16* sAhi = S_AHI(b); __nv_bfloat16* sAlo = S_ALO(b);
                __nv_bfloat16* sBhi = S_BHI(b); __nv_bfloat16* sBlo = S_BLO(b);
#pragma unroll
                for (int kk = 0; kk < 2; ++kk) {
                    wmma::fragment<wmma::matrix_a, 16, 16, 16, __nv_bfloat16, wmma::row_major> ahi[2], alo[2];
#pragma unroll
                    for (int m = 0; m < 2; ++m) {
                        const int ro = (warp_m * 32 + m * 16) * LDA + kk * 16;
                        wmma::load_matrix_sync(ahi[m], sAhi + ro, LDA);
                        wmma::load_matrix_sync(alo[m], sAlo + ro, LDA);
                    }
#pragma unroll
                    for (int n = 0; n < 2; ++n) {
                        const int co = (kk * 16) * LDB + warp_n * 32 + n * 16;
                        wmma::fragment<wmma::matrix_b, 16, 16, 16, __nv_bfloat16, wmma::row_major> bhi, blo;
                        wmma::load_matrix_sync(bhi, sBhi + co, LDB);
                        wmma::load_matrix_sync(blo, sBlo + co, LDB);
#pragma unroll
                        for (int m = 0; m < 2; ++m) {
                            wmma::mma_sync(acc[m][n], ahi[m], bhi, acc[m][n]);
                            wmma::mma_sync(acc[m][n], ahi[m], blo, acc[m][n]);
                            wmma::mma_sync(acc[m][n], alo[m], bhi, acc[m][n]);
                        }
                    }
                }

                // ---- split+store tile k+1 (register-resident) into buf nb ----
                if (k + 1 < NS) {
                    uint4 hi, lo;
                    split8(a0, a1, hi, lo);
                    *(uint4*)(S_AHI(nb) + rA * LDA + cA) = hi;
                    *(uint4*)(S_ALO(nb) + rA * LDA + cA) = lo;
#pragma unroll
                    for (int i = 0; i < 2; ++i) {
                        split8(bb[i][0], bb[i][1], hi, lo);
                        *(uint4*)(S_BHI(nb) + (rB + 16 * i) * LDB + cB) = hi;
                        *(uint4*)(S_BLO(nb) + (rB + 16 * i) * LDB + cB) = lo;
                    }
                }
                // ---- prefetch tile k+2 into registers ----
                if (k + 2 < NS) {
                    const int kn = (k + 2) * BK;
                    if (rA < rows) { a0 = *(const float4*)(arow + kn); a1 = *(const float4*)(arow + kn + 4); }
                    else           { a0 = a1 = make_float4(0.f, 0.f, 0.f, 0.f); }
#pragma unroll
                    for (int i = 0; i < 2; ++i) {
                        const float* brow = wb + (size_t)(kn + rB + 16 * i) * NTOT + cB;
                        bb[i][0] = *(const float4*)brow;
                        bb[i][1] = *(const float4*)(brow + 4);
                    }
                }
                __syncthreads();
            }

            // ---- epilogue: stage via smem, predicated vector store ----
#pragma unroll
            for (int m = 0; m < 2; ++m)
#pragma unroll
                for (int n = 0; n < 2; ++n)
                    wmma::store_matrix_sync(
                        sStage + (warp_m * 32 + m * 16) * LDB + warp_n * 32 + n * 16,
                        acc[m][n], LDB, wmma::mem_row_major);
            __syncthreads();
#pragma unroll
            for (int i = 0; i < 8; ++i) {
                int id = tid + i * NTHREADS;
                int r  = id >> 5;
                int c  = (id & 31) * 4;
                if (r < rows) {
                    float4 v = *(const float4*)(sStage + r * LDB + c);
                    *(float4*)(Out + (size_t)(row_base + r) * NTOT + n0 + c) = v;
                }
            }
            __syncthreads();
        }
    }
#undef S_AHI
#undef S_ALO
#undef S_BHI
#undef S_BLO
}

// ---------------------------------------------------------------------------
// Elementwise SwiGLU: inter = silu(gate) * up
// ---------------------------------------------------------------------------
__global__ __launch_bounds__(256)
void swiglu_kernel() {
    constexpr size_t N4 = (size_t)T_TOK * IMZ / 4;
    size_t i = (size_t)blockIdx.x * 256 + threadIdx.x;
    if (i < N4) {
        float4 g = ((const float4*)g_gate)[i];
        float4 u = ((const float4*)g_up)[i];
        float4 o;
        o.x = u.x * g.x / (1.0f + __expf(-g.x));
        o.y = u.y * g.y / (1.0f + __expf(-g.y));
        o.z = u.z * g.z / (1.0f + __expf(-g.z));
        o.w = u.w * g.w / (1.0f + __expf(-g.w));
        ((float4*)g_inter)[i] = o;
    }
}

// ---------------------------------------------------------------------------
extern "C" void kernel_launch(void* const* d_in, const int* in_sizes, int n_in,
                              void* d_out, int out_size) {
    const float* H  = (const float*)d_in[0];   // hidden_states [T, HS]
    const float* Wg = (const float*)d_in[1];   // gate_kernel   [E, HS, IMZ]
    const float* Wu = (const float*)d_in[2];   // up_kernel     [E, HS, IMZ]
    const float* Wd = (const float*)d_in[3];   // down_kernel   [E, IMZ, HS]
    const int*   gs = (const int*)d_in[4];     // group_sizes   [E]
    float* Out = (float*)d_out;                // [T, HS]

    cudaFuncSetAttribute(gemm_tc, cudaFuncAttributeMaxDynamicSharedMemorySize,
                         GEMM_SMEM);

    const int grid = 296;  // 2 blocks/SM x 148 SMs, persistent tile loop
    float* gate_p = nullptr, *up_p = nullptr, *inter_p = nullptr;
    cudaGetSymbolAddress((void**)&gate_p,  g_gate);
    cudaGetSymbolAddress((void**)&up_p,    g_up);
    cudaGetSymbolAddress((void**)&inter_p, g_inter);

    gemm_tc<<<grid, NTHREADS, GEMM_SMEM>>>(H, Wg, gate_p, gs, HS, IMZ, IMZ / BN);
    gemm_tc<<<grid, NTHREADS, GEMM_SMEM>>>(H, Wu, up_p,   gs, HS, IMZ, IMZ / BN);

    const int n4 = (int)(((size_t)T_TOK * IMZ / 4 + 255) / 256);
    swiglu_kernel<<<n4, 256>>>();

    gemm_tc<<<grid, NTHREADS, GEMM_SMEM>>>(inter_p, Wd, Out, gs, IMZ, HS, HS / BN);
}

// round 13
// speedup vs baseline: 1.2402x; 1.1371x over previous
#include <cuda_runtime.h>
#include <cuda_bf16.h>
#include <mma.h>
#include <cstdint>

using namespace nvcuda;

// Problem constants (fixed by the dataset instance)
static constexpr int T_TOK = 2048;
static constexpr int HS    = 2048;
static constexpr int IMZ   = 1408;
static constexpr int NE    = 32;

// Tiling
static constexpr int BM = 64;
static constexpr int BN = 128;
static constexpr int BK = 32;
static constexpr int NTHREADS = 256;      // 8 warps: 2 (m) x 4 (n)
static constexpr int LDA = BK + 8;        // 40 bf16 elems (80B rows; 16B-aligned cols)
static constexpr int LDB = BN + 8;        // 136 bf16 elems (272B rows; 16B-aligned cols)

// Stage: A hi/lo 2*5120B + B hi/lo 2*8704B = 27648B; double-buffered.
static constexpr int GEMM_STAGE = 27648;
static constexpr int GEMM_SMEM  = 2 * GEMM_STAGE;   // 55296
// Epilogue staging tile (aliases stage 0/1): 64*136*4 = 34816 <= 55296.

// Scratch (static device allocations are allowed; cudaMalloc is not)
__device__ float g_gate [(size_t)T_TOK * IMZ];
__device__ float g_up   [(size_t)T_TOK * IMZ];
__device__ float g_inter[(size_t)T_TOK * IMZ];

// ---------------------------------------------------------------------------
// fp32 x8 -> bf16 hi/lo split, packed as uint4 (8 bf16 = 16B) for STS.128.
// hi = rn(x), lo = rn(x - hi). bf16x3 product error ~2^-16 rel.
// ---------------------------------------------------------------------------
__device__ __forceinline__ void split8(const float4& a, const float4& b,
                                       uint4& hi, uint4& lo) {
    __nv_bfloat162 h0 = __floats2bfloat162_rn(a.x, a.y);
    __nv_bfloat162 h1 = __floats2bfloat162_rn(a.z, a.w);
    __nv_bfloat162 h2 = __floats2bfloat162_rn(b.x, b.y);
    __nv_bfloat162 h3 = __floats2bfloat162_rn(b.z, b.w);
    float2 f0 = __bfloat1622float2(h0);
    float2 f1 = __bfloat1622float2(h1);
    float2 f2 = __bfloat1622float2(h2);
    float2 f3 = __bfloat1622float2(h3);
    __nv_bfloat162 l0 = __floats2bfloat162_rn(a.x - f0.x, a.y - f0.y);
    __nv_bfloat162 l1 = __floats2bfloat162_rn(a.z - f1.x, a.w - f1.y);
    __nv_bfloat162 l2 = __floats2bfloat162_rn(b.x - f2.x, b.y - f2.y);
    __nv_bfloat162 l3 = __floats2bfloat162_rn(b.z - f3.x, b.w - f3.y);
    hi.x = *(const uint32_t*)&h0; hi.y = *(const uint32_t*)&h1;
    hi.z = *(const uint32_t*)&h2; hi.w = *(const uint32_t*)&h3;
    lo.x = *(const uint32_t*)&l0; lo.y = *(const uint32_t*)&l1;
    lo.z = *(const uint32_t*)&l2; lo.w = *(const uint32_t*)&l3;
}

// ---------------------------------------------------------------------------
// Unified grouped GEMM over a tile pool that can span TWO weight/output pairs
// (gate and up run as one launch for load balance; wave>=2 work-stealing fills
// slots).  Tile t < ntiles_per: Out1 = A @ B1; else Out2 = A @ B2.
// A: [T, K] fp32.  B: [E, K, NTOT] fp32 (n contiguous).  bf16x3 via HMMA,
// 2-stage smem pipeline with register prefetch, one barrier per k-iter.
// Grid = total tile count (non-persistent; one tile per CTA).
// ---------------------------------------------------------------------------
__global__ __launch_bounds__(NTHREADS, 2)
void gemm_tc(const float* __restrict__ A,
             const float* __restrict__ B1, float* __restrict__ Out1,
             const float* __restrict__ B2, float* __restrict__ Out2,
             const int* __restrict__ gs,
             int K, int NTOT, int nx, int ntiles_per)
{
    extern __shared__ __align__(16) char ds[];
    __shared__ int s_ofs[NE + 1];

#define S_AHI(s) ((__nv_bfloat16*)(ds + (s) * GEMM_STAGE))
#define S_ALO(s) ((__nv_bfloat16*)(ds + (s) * GEMM_STAGE + 5120))
#define S_BHI(s) ((__nv_bfloat16*)(ds + (s) * GEMM_STAGE + 10240))
#define S_BLO(s) ((__nv_bfloat16*)(ds + (s) * GEMM_STAGE + 18944))
    float* sStage = (float*)ds;  // epilogue staging (after final bar)

    const int tid = threadIdx.x;
    const int wid = tid >> 5;
    const int warp_m = wid >> 2;   // 0..1 -> 32 rows
    const int warp_n = wid & 3;    // 0..3 -> 32 cols

    // Expert-offset prefix.
    if (tid < 32) {
        int g = (tid < NE) ? gs[tid] : 0;
        int v = g;
#pragma unroll
        for (int d = 1; d < 32; d <<= 1) {
            int t = __shfl_up_sync(0xffffffffu, v, d);
            if (tid >= d) v += t;
        }
        if (tid < NE) s_ofs[tid + 1] = v;
        if (tid == 0) s_ofs[0] = 0;
    }
    __syncthreads();

    // Tile select (gate vs up pool)
    int t = blockIdx.x;
    const float* B   = (t < ntiles_per) ? B1 : B2;
    float*       Out = (t < ntiles_per) ? Out1 : Out2;
    if (t >= ntiles_per) t -= ntiles_per;

    const int e  = t / nx;
    const int n0 = (t - e * nx) * BN;
    const int off0 = s_ofs[e], off1 = s_ofs[e + 1];
    const float* wb = B + (size_t)e * K * NTOT + n0;

    // Per-thread load coords (8 contiguous fp32 per thread)
    const int rA = tid >> 2;            // 0..63
    const int cA = (tid & 3) * 8;       // 0..24
    const int rB = tid >> 4;            // 0..15 (+16 for group 1)
    const int cB = (tid & 15) * 8;      // 0..120

    const int NS = K >> 5;              // K / BK

    for (int row_base = off0; row_base < off1; row_base += BM) {
        const int rows = min(BM, off1 - row_base);

        wmma::fragment<wmma::accumulator, 16, 16, 16, float> acc[2][2];
#pragma unroll
        for (int m = 0; m < 2; ++m)
#pragma unroll
            for (int n = 0; n < 2; ++n) wmma::fill_fragment(acc[m][n], 0.0f);

        float4 a0, a1, bb[2][2];
        const float* arow = A + (size_t)(row_base + rA) * K + cA;

        // ---- prologue: tile 0 -> regs -> buf0; tile 1 -> regs ----
        if (rA < rows) { a0 = *(const float4*)arow; a1 = *(const float4*)(arow + 4); }
        else           { a0 = a1 = make_float4(0.f, 0.f, 0.f, 0.f); }
#pragma unroll
        for (int i = 0; i < 2; ++i) {
            const float* brow = wb + (size_t)(rB + 16 * i) * NTOT + cB;
            bb[i][0] = *(const float4*)brow;
            bb[i][1] = *(const float4*)(brow + 4);
        }
        {
            uint4 hi, lo;
            split8(a0, a1, hi, lo);
            *(uint4*)(S_AHI(0) + rA * LDA + cA) = hi;
            *(uint4*)(S_ALO(0) + rA * LDA + cA) = lo;
#pragma unroll
            for (int i = 0; i < 2; ++i) {
                split8(bb[i][0], bb[i][1], hi, lo);
                *(uint4*)(S_BHI(0) + (rB + 16 * i) * LDB + cB) = hi;
                *(uint4*)(S_BLO(0) + (rB + 16 * i) * LDB + cB) = lo;
            }
        }
        if (NS > 1) {
            if (rA < rows) { a0 = *(const float4*)(arow + BK); a1 = *(const float4*)(arow + BK + 4); }
            else           { a0 = a1 = make_float4(0.f, 0.f, 0.f, 0.f); }
#pragma unroll
            for (int i = 0; i < 2; ++i) {
                const float* brow = wb + (size_t)(BK + rB + 16 * i) * NTOT + cB;
                bb[i][0] = *(const float4*)brow;
                bb[i][1] = *(const float4*)(brow + 4);
            }
        }
        __syncthreads();

        for (int k = 0; k < NS; ++k) {
            const int b  = k & 1;
            const int nb = b ^ 1;

            // ---- MMA on buf b ----
            __nv_bfloat16* sAhi = S_AHI(b); __nv_bfloat16* sAlo = S_ALO(b);
            __nv_bfloat16* sBhi = S_BHI(b); __nv_bfloat16* sBlo = S_BLO(b);
#pragma unroll
            for (int kk = 0; kk < 2; ++kk) {
                wmma::fragment<wmma::matrix_a, 16, 16, 16, __nv_bfloat16, wmma::row_major> ahi[2], alo[2];
#pragma unroll
                for (int m = 0; m < 2; ++m) {
                    const int ro = (warp_m * 32 + m * 16) * LDA + kk * 16;
                    wmma::load_matrix_sync(ahi[m], sAhi + ro, LDA);
                    wmma::load_matrix_sync(alo[m], sAlo + ro, LDA);
                }
#pragma unroll
                for (int n = 0; n < 2; ++n) {
                    const int co = (kk * 16) * LDB + warp_n * 32 + n * 16;
                    wmma::fragment<wmma::matrix_b, 16, 16, 16, __nv_bfloat16, wmma::row_major> bhi, blo;
                    wmma::load_matrix_sync(bhi, sBhi + co, LDB);
                    wmma::load_matrix_sync(blo, sBlo + co, LDB);
#pragma unroll
                    for (int m = 0; m < 2; ++m) {
                        wmma::mma_sync(acc[m][n], ahi[m], bhi, acc[m][n]);
                        wmma::mma_sync(acc[m][n], ahi[m], blo, acc[m][n]);
                        wmma::mma_sync(acc[m][n], alo[m], bhi, acc[m][n]);
                    }
                }
            }

            // ---- split+store tile k+1 (register-resident) into buf nb ----
            if (k + 1 < NS) {
                uint4 hi, lo;
                split8(a0, a1, hi, lo);
                *(uint4*)(S_AHI(nb) + rA * LDA + cA) = hi;
                *(uint4*)(S_ALO(nb) + rA * LDA + cA) = lo;
#pragma unroll
                for (int i = 0; i < 2; ++i) {
                    split8(bb[i][0], bb[i][1], hi, lo);
                    *(uint4*)(S_BHI(nb) + (rB + 16 * i) * LDB + cB) = hi;
                    *(uint4*)(S_BLO(nb) + (rB + 16 * i) * LDB + cB) = lo;
                }
            }
            // ---- prefetch tile k+2 into registers ----
            if (k + 2 < NS) {
                const int kn = (k + 2) * BK;
                if (rA < rows) { a0 = *(const float4*)(arow + kn); a1 = *(const float4*)(arow + kn + 4); }
                else           { a0 = a1 = make_float4(0.f, 0.f, 0.f, 0.f); }
#pragma unroll
                for (int i = 0; i < 2; ++i) {
                    const float* brow = wb + (size_t)(kn + rB + 16 * i) * NTOT + cB;
                    bb[i][0] = *(const float4*)brow;
                    bb[i][1] = *(const float4*)(brow + 4);
                }
            }
            __syncthreads();
        }

        // ---- epilogue: stage via smem, predicated vector store ----
#pragma unroll
        for (int m = 0; m < 2; ++m)
#pragma unroll
            for (int n = 0; n < 2; ++n)
                wmma::store_matrix_sync(
                    sStage + (warp_m * 32 + m * 16) * LDB + warp_n * 32 + n * 16,
                    acc[m][n], LDB, wmma::mem_row_major);
        __syncthreads();
#pragma unroll
        for (int i = 0; i < 8; ++i) {
            int id = tid + i * NTHREADS;
            int r  = id >> 5;
            int c  = (id & 31) * 4;
            if (r < rows) {
                float4 v = *(const float4*)(sStage + r * LDB + c);
                *(float4*)(Out + (size_t)(row_base + r) * NTOT + n0 + c) = v;
            }
        }
        __syncthreads();
    }
#undef S_AHI
#undef S_ALO
#undef S_BHI
#undef S_BLO
}

// ---------------------------------------------------------------------------
// Elementwise SwiGLU: inter = silu(gate) * up
// ---------------------------------------------------------------------------
__global__ __launch_bounds__(256)
void swiglu_kernel() {
    constexpr size_t N4 = (size_t)T_TOK * IMZ / 4;
    size_t i = (size_t)blockIdx.x * 256 + threadIdx.x;
    if (i < N4) {
        float4 g = ((const float4*)g_gate)[i];
        float4 u = ((const float4*)g_up)[i];
        float4 o;
        o.x = u.x * g.x / (1.0f + __expf(-g.x));
        o.y = u.y * g.y / (1.0f + __expf(-g.y));
        o.z = u.z * g.z / (1.0f + __expf(-g.z));
        o.w = u.w * g.w / (1.0f + __expf(-g.w));
        ((float4*)g_inter)[i] = o;
    }
}

// ---------------------------------------------------------------------------
extern "C" void kernel_launch(void* const* d_in, const int* in_sizes, int n_in,
                              void* d_out, int out_size) {
    const float* H  = (const float*)d_in[0];   // hidden_states [T, HS]
    const float* Wg = (const float*)d_in[1];   // gate_kernel   [E, HS, IMZ]
    const float* Wu = (const float*)d_in[2];   // up_kernel     [E, HS, IMZ]
    const float* Wd = (const float*)d_in[3];   // down_kernel   [E, IMZ, HS]
    const int*   gs = (const int*)d_in[4];     // group_sizes   [E]
    float* Out = (float*)d_out;                // [T, HS]

    cudaFuncSetAttribute(gemm_tc, cudaFuncAttributeMaxDynamicSharedMemorySize,
                         GEMM_SMEM);

    float* gate_p = nullptr, *up_p = nullptr, *inter_p = nullptr;
    cudaGetSymbolAddress((void**)&gate_p,  g_gate);
    cudaGetSymbolAddress((void**)&up_p,    g_up);
    cudaGetSymbolAddress((void**)&inter_p, g_inter);

    // Gate + Up as ONE tile pool (704 tiles) for load balance.
    const int nt_gu = (IMZ / BN) * NE;   // 352
    gemm_tc<<<2 * nt_gu, NTHREADS, GEMM_SMEM>>>(
        H, Wg, gate_p, Wu, up_p, gs, HS, IMZ, IMZ / BN, nt_gu);

    const int n4 = (int)(((size_t)T_TOK * IMZ / 4 + 255) / 256);
    swiglu_kernel<<<n4, 256>>>();

    // Down: 512 tiles.
    const int nt_dn = (HS / BN) * NE;    // 512
    gemm_tc<<<nt_dn, NTHREADS, GEMM_SMEM>>>(
        inter_p, Wd, Out, Wd, Out, gs, IMZ, HS, HS / BN, nt_dn);
}